// round 1
// baseline (speedup 1.0000x reference)
#include <cuda_runtime.h>
#include <math.h>

#define B_  16
#define N_  4096
#define C_  512
#define H_  8
#define D_  64
#define CK_ 1024
#define SPLITS 16

// -------- scratch (device globals; no runtime allocation) --------
__device__ float g_qk[(size_t)B_ * N_ * CK_];        // 256 MB: elu(q)+1 | elu(k)+1, (b,n,1024)
__device__ float g_cos[N_ * 256];
__device__ float g_sin[N_ * 256];
__device__ float g_kmean[B_ * C_];
__device__ float g_kvp[SPLITS * B_ * H_ * D_ * D_];
__device__ float g_kv[B_ * H_ * D_ * D_];

// -------- f32x2 packed math helpers (sm_103a) --------
__device__ __forceinline__ unsigned long long dup2(float a) {
    unsigned long long r;
    asm("mov.b64 %0, {%1, %1};" : "=l"(r) : "f"(a));
    return r;
}
__device__ __forceinline__ unsigned long long pack2(float lo, float hi) {
    unsigned long long r;
    asm("mov.b64 %0, {%1, %2};" : "=l"(r) : "f"(lo), "f"(hi));
    return r;
}
__device__ __forceinline__ void unpack2(unsigned long long v, float& lo, float& hi) {
    asm("mov.b64 {%0, %1}, %2;" : "=f"(lo), "=f"(hi) : "l"(v));
}
#define FMA2(acc, a, b) asm("fma.rn.f32x2 %0, %1, %2, %0;" : "+l"(acc) : "l"(a), "l"(b))

// ============================================================
// K0: RoPE cos/sin table.  index = n*256 + k,  k in [0,256)
//     k < 128: angle = hpos * theta[k];  k >= 128: angle = wpos * theta[k-128]
// ============================================================
__global__ void rope_init_kernel() {
    int idx = blockIdx.x * blockDim.x + threadIdx.x;
    if (idx >= N_ * 256) return;
    int n  = idx >> 8;
    int k  = idx & 255;
    int hp = n >> 6, wp = n & 63;
    int kk = k & 127;
    float pos   = (k < 128) ? (float)hp : (float)wp;
    float theta = powf(10000.0f, -(float)kk / 128.0f);
    float a = pos * theta;
    g_cos[idx] = cosf(a);
    g_sin[idx] = sinf(a);
}

// ============================================================
// K1: qk = elu(x @ W + bias) + 1.  M=65536, K=512, N=1024.
//     128x128 block tile, BK=8, 8x8 per thread, packed f32x2 FMAs.
// ============================================================
__global__ __launch_bounds__(256, 2)
void qk_gemm_kernel(const float* __restrict__ X, const float* __restrict__ W,
                    const float* __restrict__ bias) {
    __shared__ float As[8][128];
    __shared__ float Bs[8][128];

    const int tid = threadIdx.x;
    const int m0 = blockIdx.y * 128;
    const int j0 = blockIdx.x * 128;
    const int ty = tid >> 4, tx = tid & 15;

    unsigned long long acc2[8][4];
#pragma unroll
    for (int i = 0; i < 8; i++)
#pragma unroll
        for (int j = 0; j < 4; j++) acc2[i][j] = 0ULL;

    const int arow = tid >> 1, acol = (tid & 1) * 4;
    const int brow = tid >> 5, bcol = (tid & 31) * 4;

    for (int k0 = 0; k0 < 512; k0 += 8) {
        float4 av = *(const float4*)&X[(size_t)(m0 + arow) * 512 + k0 + acol];
        float4 bv = *(const float4*)&W[(size_t)(k0 + brow) * 1024 + j0 + bcol];
        As[acol + 0][arow] = av.x;
        As[acol + 1][arow] = av.y;
        As[acol + 2][arow] = av.z;
        As[acol + 3][arow] = av.w;
        *(float4*)&Bs[brow][bcol] = bv;
        __syncthreads();

#pragma unroll
        for (int kk = 0; kk < 8; kk++) {
            float4 a0 = *(const float4*)&As[kk][ty * 8];
            float4 a1 = *(const float4*)&As[kk][ty * 8 + 4];
            float4 b0 = *(const float4*)&Bs[kk][tx * 8];
            float4 b1 = *(const float4*)&Bs[kk][tx * 8 + 4];
            unsigned long long bb[4];
            bb[0] = pack2(b0.x, b0.y);
            bb[1] = pack2(b0.z, b0.w);
            bb[2] = pack2(b1.x, b1.y);
            bb[3] = pack2(b1.z, b1.w);
            unsigned long long ad[8];
            ad[0] = dup2(a0.x); ad[1] = dup2(a0.y); ad[2] = dup2(a0.z); ad[3] = dup2(a0.w);
            ad[4] = dup2(a1.x); ad[5] = dup2(a1.y); ad[6] = dup2(a1.z); ad[7] = dup2(a1.w);
#pragma unroll
            for (int i = 0; i < 8; i++) {
                FMA2(acc2[i][0], ad[i], bb[0]);
                FMA2(acc2[i][1], ad[i], bb[1]);
                FMA2(acc2[i][2], ad[i], bb[2]);
                FMA2(acc2[i][3], ad[i], bb[3]);
            }
        }
        __syncthreads();
    }

    // epilogue: +bias, elu+1, coalesced float4 stores
#pragma unroll
    for (int i = 0; i < 8; i++) {
        const int m = m0 + ty * 8 + i;
        float ov[8];
#pragma unroll
        for (int jp = 0; jp < 4; jp++) unpack2(acc2[i][jp], ov[2 * jp], ov[2 * jp + 1]);
#pragma unroll
        for (int j = 0; j < 8; j++) {
            const int col = j0 + tx * 8 + j;
            float v = ov[j] + bias[col];
            ov[j] = (v > 0.f) ? (v + 1.f) : __expf(v);
        }
        float4 o0 = make_float4(ov[0], ov[1], ov[2], ov[3]);
        float4 o1 = make_float4(ov[4], ov[5], ov[6], ov[7]);
        *(float4*)&g_qk[(size_t)m * 1024 + j0 + tx * 8]     = o0;
        *(float4*)&g_qk[(size_t)m * 1024 + j0 + tx * 8 + 4] = o1;
    }
}

// ============================================================
// K2: kmean[b, c] = mean_n k_post[b, n, c]   (c in [0,512))
// ============================================================
__global__ void kmean_kernel() {
    const int b   = blockIdx.y;
    const int col = blockIdx.x * 128 + threadIdx.x;
    float s = 0.f;
#pragma unroll 8
    for (int n = 0; n < N_; n++)
        s += g_qk[((size_t)(b * N_ + n)) * CK_ + C_ + col];
    g_kmean[b * C_ + col] = s * (1.0f / N_);
}

// ============================================================
// K3: split-K partial kv:  kvp[s,b,h,d,e] = sum_{n in split} krope(n,d) * v(n,e)
//     v(b,h,n,e) = x[b,n,h*64+e].  RoPE applied on the fly via table.
// ============================================================
__global__ __launch_bounds__(256)
void kv_partial_kernel(const float* __restrict__ X) {
    const int split = blockIdx.x, h = blockIdx.y, b = blockIdx.z;
    __shared__ float ks[16][64];
    __shared__ float vs[16][64];

    const int tid = threadIdx.x;
    const int ty = tid >> 4, tx = tid & 15;
    const int n0 = split * (N_ / SPLITS);

    float acc[4][4];
#pragma unroll
    for (int i = 0; i < 4; i++)
#pragma unroll
        for (int j = 0; j < 4; j++) acc[i][j] = 0.f;

    for (int c0 = 0; c0 < N_ / SPLITS; c0 += 16) {
        // load + rotate K tile (16 rows x 32 pairs)
#pragma unroll
        for (int l = 0; l < 2; l++) {
            const int p   = tid + l * 256;        // 0..511
            const int row = p >> 5, kd = p & 31;
            const int n   = n0 + c0 + row;
            const float2 kq = *(const float2*)&g_qk[((size_t)(b * N_ + n)) * CK_ + C_ + h * D_ + 2 * kd];
            const int ci = n * 256 + h * 32 + kd;
            const float cc = g_cos[ci], ss = g_sin[ci];
            float2 kr;
            kr.x = kq.x * cc - kq.y * ss;
            kr.y = kq.x * ss + kq.y * cc;
            *(float2*)&ks[row][2 * kd] = kr;
        }
        // load V tile (16 rows x 64)
        {
            const int row = tid >> 4;
            const int e4  = (tid & 15) * 4;
            const int n   = n0 + c0 + row;
            *(float4*)&vs[row][e4] =
                *(const float4*)&X[((size_t)(b * N_ + n)) * C_ + h * D_ + e4];
        }
        __syncthreads();

#pragma unroll
        for (int nn = 0; nn < 16; nn++) {
            float kr[4], vr[4];
#pragma unroll
            for (int i = 0; i < 4; i++) kr[i] = ks[nn][ty * 4 + i];
#pragma unroll
            for (int j = 0; j < 4; j++) vr[j] = vs[nn][tx * 4 + j];
#pragma unroll
            for (int i = 0; i < 4; i++)
#pragma unroll
                for (int j = 0; j < 4; j++) acc[i][j] += kr[i] * vr[j];
        }
        __syncthreads();
    }

    float* dst = &g_kvp[(((size_t)split * B_ + b) * H_ + h) * (D_ * D_)];
#pragma unroll
    for (int i = 0; i < 4; i++)
#pragma unroll
        for (int j = 0; j < 4; j++)
            dst[(ty * 4 + i) * D_ + tx * 4 + j] = acc[i][j];
}

// ============================================================
// K4: kv = (1/N) * sum_splits kvp    (scale^2 = 1/n)
// ============================================================
__global__ void kv_reduce_kernel() {
    const int i = blockIdx.x * 256 + threadIdx.x;   // < B*H*64*64
    float s = 0.f;
#pragma unroll
    for (int sp = 0; sp < SPLITS; sp++)
        s += g_kvp[(size_t)sp * (B_ * H_ * D_ * D_) + i];
    g_kv[i] = s * (1.0f / N_);
}

// ============================================================
// K5: finalize.  Per block: (b, h, spatial row hp) = 64 tokens x 64 channels.
//     out = (q_rope @ kv) * z + lepe,  lepe fused depthwise 3x3 on x.
// ============================================================
__global__ __launch_bounds__(256)
void finalize_kernel(const float* __restrict__ X, const float* __restrict__ LW,
                     const float* __restrict__ LB, float* __restrict__ out) {
    const int hp = blockIdx.x;   // spatial row == n-tile of 64
    const int h  = blockIdx.y;
    const int b  = blockIdx.z;

    __shared__ float kvs[64][64];
    __shared__ float qs[64][64];
    __shared__ float zs[64];
    __shared__ float km[64];
    __shared__ float w9s[9][64];

    const int tid = threadIdx.x;

    // load kv tile
    {
        const float* kvsrc = &g_kv[((size_t)(b * H_ + h)) * (D_ * D_)];
        for (int i = tid; i < 1024; i += 256)
            ((float4*)kvs)[i] = ((const float4*)kvsrc)[i];
    }
    if (tid < 64) km[tid] = g_kmean[b * C_ + h * D_ + tid];
    for (int i = tid; i < 576; i += 256) {
        const int p = i / 64, e = i % 64;
        w9s[p][e] = LW[p * C_ + h * D_ + e];
    }
    __syncthreads();

    // q-RoPE + z (one warp handles 8 rows; lane = pair index)
    {
        const int w = tid >> 5, lane = tid & 31;
#pragma unroll
        for (int rr = 0; rr < 8; rr++) {
            const int r = w * 8 + rr;
            const int n = hp * 64 + r;
            const float2 qv = *(const float2*)&g_qk[((size_t)(b * N_ + n)) * CK_ + h * D_ + 2 * lane];
            const int ci = n * 256 + h * 32 + lane;
            const float cc = g_cos[ci], ss = g_sin[ci];
            float2 qr;
            qr.x = qv.x * cc - qv.y * ss;
            qr.y = qv.x * ss + qv.y * cc;
            *(float2*)&qs[r][2 * lane] = qr;
            float zp = qv.x * km[2 * lane] + qv.y * km[2 * lane + 1];
#pragma unroll
            for (int o = 16; o > 0; o >>= 1) zp += __shfl_xor_sync(0xffffffffu, zp, o);
            if (lane == 0) zs[r] = 1.0f / (zp + 1e-6f);
        }
    }
    __syncthreads();

    // matvec + lepe
    const int e = tid & 63;
    const int c = h * D_ + e;
    const float lbias = LB[c];
    for (int r = tid >> 6; r < 64; r += 4) {
        float acc = 0.f;
#pragma unroll
        for (int d = 0; d < 64; d++) acc += qs[r][d] * kvs[d][e];

        float lep = lbias;
#pragma unroll
        for (int di = 0; di < 3; di++) {
            const int h2 = hp + di - 1;
            if ((unsigned)h2 < 64u) {
#pragma unroll
                for (int dj = 0; dj < 3; dj++) {
                    const int w2 = r + dj - 1;
                    if ((unsigned)w2 < 64u)
                        lep += X[((size_t)(b * N_ + h2 * 64 + w2)) * C_ + c] * w9s[di * 3 + dj][e];
                }
            }
        }
        out[((size_t)(b * N_ + hp * 64 + r)) * C_ + c] = acc * zs[r] + lep;
    }
}

// ============================================================
extern "C" void kernel_launch(void* const* d_in, const int* in_sizes, int n_in,
                              void* d_out, int out_size) {
    (void)in_sizes; (void)n_in; (void)out_size;
    const float* x  = (const float*)d_in[0];   // (16, 4096, 512)
    const float* W  = (const float*)d_in[1];   // (512, 1024)
    const float* qb = (const float*)d_in[2];   // (1024,)
    const float* lw = (const float*)d_in[3];   // (3,3,1,512)
    const float* lb = (const float*)d_in[4];   // (512,)
    float* out = (float*)d_out;                // (16, 4096, 512)

    rope_init_kernel<<<(N_ * 256 + 255) / 256, 256>>>();
    qk_gemm_kernel<<<dim3(CK_ / 128, (B_ * N_) / 128), 256>>>(x, W, qb);
    kmean_kernel<<<dim3(C_ / 128, B_), 128>>>();
    kv_partial_kernel<<<dim3(SPLITS, H_, B_), 256>>>(x);
    kv_reduce_kernel<<<(B_ * H_ * D_ * D_) / 256, 256>>>();
    finalize_kernel<<<dim3(64, H_, B_), 256>>>(x, lw, lb, out);
}

// round 4
// speedup vs baseline: 1.4492x; 1.4492x over previous
#include <cuda_runtime.h>
#include <cuda_bf16.h>
#include <cstdint>
#include <math.h>

#define B_  16
#define N_  4096
#define C_  512
#define H_  8
#define D_  64
#define CK_ 1024
#define SPLITS 16

// -------- scratch (device globals; no runtime allocation) --------
__device__ float g_qk[(size_t)B_ * N_ * CK_];        // elu(q)+1 | elu(k)+1, (b,n,1024)
__device__ float g_cos[N_ * 256];
__device__ float g_sin[N_ * 256];
__device__ float g_kmean[B_ * C_];
__device__ float g_kvp[SPLITS * B_ * H_ * D_ * D_];
__device__ float g_kv[B_ * H_ * D_ * D_];
// bf16 hi/lo split operands
__device__ __nv_bfloat16 g_Ahi[(size_t)B_ * N_ * C_];   // [65536][512]
__device__ __nv_bfloat16 g_Alo[(size_t)B_ * N_ * C_];
__device__ __nv_bfloat16 g_Whi[CK_ * C_];               // transposed: [1024][512] K-major
__device__ __nv_bfloat16 g_Wlo[CK_ * C_];

// ============ PTX helpers (plain sm_103-safe: mma.sync / ldmatrix / cp.async) ============
__device__ __forceinline__ uint32_t smem_u32(const void* p) {
    uint32_t a;
    asm("{ .reg .u64 t; cvta.to.shared.u64 t, %1; cvt.u32.u64 %0, t; }" : "=r"(a) : "l"(p));
    return a;
}
__device__ __forceinline__ void cp16(uint32_t dst, const void* src) {
    asm volatile("cp.async.cg.shared.global [%0], [%1], 16;" :: "r"(dst), "l"(src) : "memory");
}
#define CP_COMMIT() asm volatile("cp.async.commit_group;" ::: "memory")
#define CP_WAIT(n)  asm volatile("cp.async.wait_group %0;" :: "n"(n) : "memory")

__device__ __forceinline__ void ldsm_x4(uint32_t (&r)[4], uint32_t addr) {
    asm volatile("ldmatrix.sync.aligned.m8n8.x4.shared.b16 {%0,%1,%2,%3}, [%4];"
                 : "=r"(r[0]), "=r"(r[1]), "=r"(r[2]), "=r"(r[3]) : "r"(addr));
}
__device__ __forceinline__ void mma16816(float (&c)[4], const uint32_t (&a)[4],
                                         uint32_t b0, uint32_t b1) {
    asm volatile(
        "mma.sync.aligned.m16n8k16.row.col.f32.bf16.bf16.f32 "
        "{%0,%1,%2,%3}, {%4,%5,%6,%7}, {%8,%9}, {%0,%1,%2,%3};"
        : "+f"(c[0]), "+f"(c[1]), "+f"(c[2]), "+f"(c[3])
        : "r"(a[0]), "r"(a[1]), "r"(a[2]), "r"(a[3]), "r"(b0), "r"(b1));
}

// ============================================================
// K0: RoPE cos/sin table.
// ============================================================
__global__ void rope_init_kernel() {
    int idx = blockIdx.x * blockDim.x + threadIdx.x;
    if (idx >= N_ * 256) return;
    int n  = idx >> 8;
    int k  = idx & 255;
    int hp = n >> 6, wp = n & 63;
    int kk = k & 127;
    float pos   = (k < 128) ? (float)hp : (float)wp;
    float theta = powf(10000.0f, -(float)kk / 128.0f);
    float a = pos * theta;
    g_cos[idx] = cosf(a);
    g_sin[idx] = sinf(a);
}

// ============================================================
// converts: fp32 -> bf16 hi/lo
// ============================================================
__global__ void convert_x_kernel(const float* __restrict__ X) {
    size_t i = ((size_t)blockIdx.x * 256 + threadIdx.x) * 4;
    float4 v = *(const float4*)(X + i);
    __nv_bfloat16 hv[4], lv[4];
    float f[4] = {v.x, v.y, v.z, v.w};
#pragma unroll
    for (int j = 0; j < 4; j++) {
        hv[j] = __float2bfloat16(f[j]);
        lv[j] = __float2bfloat16(f[j] - __bfloat162float(hv[j]));
    }
    *(uint2*)(g_Ahi + i) = *(uint2*)hv;
    *(uint2*)(g_Alo + i) = *(uint2*)lv;
}

__global__ void convert_w_kernel(const float* __restrict__ W) {
    int i = blockIdx.x * 256 + threadIdx.x;   // over 512*1024
    int k = i >> 10, n = i & 1023;
    float v = W[i];
    __nv_bfloat16 h = __float2bfloat16(v);
    __nv_bfloat16 l = __float2bfloat16(v - __bfloat162float(h));
    g_Whi[n * 512 + k] = h;
    g_Wlo[n * 512 + k] = l;
}

// ============================================================
// K1: mma.sync bf16x3 GEMM: g_qk = elu(X @ W + bias) + 1
//     CTA tile 128(M) x 128(N), BK=32, 8 warps (32x64 each),
//     cp.async double-buffered, 80B-padded smem rows.
// ============================================================
#define BK      32
#define ROWB    80                   // smem row stride bytes (40 bf16)
#define BUF_SZ  (128 * ROWB)         // 10240 bytes per operand tile
#define STG_SZ  (4 * BUF_SZ)         // Ahi,Alo,Bhi,Blo = 40960
#define GSMEM   (2 * STG_SZ)         // 81920

__global__ __launch_bounds__(256, 2)
void qk_gemm_mma(const float* __restrict__ bias) {
    extern __shared__ char smem[];
    const uint32_t sb = smem_u32(smem);

    const int tid  = threadIdx.x;
    const int warp = tid >> 5, lane = tid & 31;
    const int wm = warp & 3;          // 4 warps along M (32 rows each)
    const int wn = warp >> 2;         // 2 warps along N (64 cols each)
    const int n0 = blockIdx.x * 128;
    const int m0 = blockIdx.y * 128;

    // gmem->smem mapping: chunk c in [0,512): row=c>>2, col16=c&3
    const int c0r = tid >> 2,            c0c = (tid & 3);
    const int c1r = (tid + 256) >> 2,    c1c = c0c;
    const __nv_bfloat16* srcA0h; const __nv_bfloat16* srcB0h;

    float acc[2][8][4];
#pragma unroll
    for (int a = 0; a < 2; a++)
#pragma unroll
        for (int b = 0; b < 8; b++)
#pragma unroll
            for (int c = 0; c < 4; c++) acc[a][b][c] = 0.f;

    // prefetch helper (stage s, k-offset k0)
    auto prefetch = [&](int s, int k0) {
        const uint32_t st = sb + s * STG_SZ;
        const size_t gA0 = (size_t)(m0 + c0r) * 512 + k0 + c0c * 8;
        const size_t gA1 = (size_t)(m0 + c1r) * 512 + k0 + c1c * 8;
        const size_t gB0 = (size_t)(n0 + c0r) * 512 + k0 + c0c * 8;
        const size_t gB1 = (size_t)(n0 + c1r) * 512 + k0 + c1c * 8;
        const uint32_t s0 = c0r * ROWB + c0c * 16;
        const uint32_t s1 = c1r * ROWB + c1c * 16;
        cp16(st + 0 * BUF_SZ + s0, g_Ahi + gA0);
        cp16(st + 0 * BUF_SZ + s1, g_Ahi + gA1);
        cp16(st + 1 * BUF_SZ + s0, g_Alo + gA0);
        cp16(st + 1 * BUF_SZ + s1, g_Alo + gA1);
        cp16(st + 2 * BUF_SZ + s0, g_Whi + gB0);
        cp16(st + 2 * BUF_SZ + s1, g_Whi + gB1);
        cp16(st + 3 * BUF_SZ + s0, g_Wlo + gB0);
        cp16(st + 3 * BUF_SZ + s1, g_Wlo + gB1);
    };

    prefetch(0, 0);
    CP_COMMIT();

    // per-lane ldmatrix base offsets (within a buffer)
    const uint32_t aoff = (wm * 32 + (lane & 15)) * ROWB + (lane >> 4) * 16;
    const uint32_t boff = (wn * 64 + (lane & 15)) * ROWB + (lane >> 4) * 16;

#pragma unroll 1
    for (int ks = 0; ks < 16; ks++) {
        if (ks < 15) { prefetch((ks + 1) & 1, (ks + 1) * BK); CP_COMMIT(); CP_WAIT(1); }
        else         { CP_WAIT(0); }
        __syncthreads();

        const uint32_t st = sb + (ks & 1) * STG_SZ;
#pragma unroll
        for (int kk = 0; kk < 2; kk++) {            // two k16 steps in BK=32
            const uint32_t kb = kk * 32;
            uint32_t ah[2][4], al[2][4], bh[4][4], bl[4][4];
#pragma unroll
            for (int mt = 0; mt < 2; mt++) {
                ldsm_x4(ah[mt], st + 0 * BUF_SZ + aoff + mt * (16 * ROWB) + kb);
                ldsm_x4(al[mt], st + 1 * BUF_SZ + aoff + mt * (16 * ROWB) + kb);
            }
#pragma unroll
            for (int nt = 0; nt < 4; nt++) {
                ldsm_x4(bh[nt], st + 2 * BUF_SZ + boff + nt * (16 * ROWB) + kb);
                ldsm_x4(bl[nt], st + 3 * BUF_SZ + boff + nt * (16 * ROWB) + kb);
            }
#pragma unroll
            for (int mt = 0; mt < 2; mt++) {
#pragma unroll
                for (int nt = 0; nt < 4; nt++) {
                    // hi*hi
                    mma16816(acc[mt][2 * nt + 0], ah[mt], bh[nt][0], bh[nt][2]);
                    mma16816(acc[mt][2 * nt + 1], ah[mt], bh[nt][1], bh[nt][3]);
                    // hi*lo
                    mma16816(acc[mt][2 * nt + 0], ah[mt], bl[nt][0], bl[nt][2]);
                    mma16816(acc[mt][2 * nt + 1], ah[mt], bl[nt][1], bl[nt][3]);
                    // lo*hi
                    mma16816(acc[mt][2 * nt + 0], al[mt], bh[nt][0], bh[nt][2]);
                    mma16816(acc[mt][2 * nt + 1], al[mt], bh[nt][1], bh[nt][3]);
                }
            }
        }
        __syncthreads();
    }

    // epilogue: +bias, elu+1, float2 stores
#pragma unroll
    for (int mt = 0; mt < 2; mt++) {
        const int row0 = m0 + wm * 32 + mt * 16 + (lane >> 2);
#pragma unroll
        for (int nt = 0; nt < 8; nt++) {
            const int col = n0 + wn * 64 + nt * 8 + (lane & 3) * 2;
            const float b0 = __ldg(&bias[col]);
            const float b1 = __ldg(&bias[col + 1]);
            float v0 = acc[mt][nt][0] + b0;
            float v1 = acc[mt][nt][1] + b1;
            float v2 = acc[mt][nt][2] + b0;
            float v3 = acc[mt][nt][3] + b1;
            v0 = (v0 > 0.f) ? (v0 + 1.f) : __expf(v0);
            v1 = (v1 > 0.f) ? (v1 + 1.f) : __expf(v1);
            v2 = (v2 > 0.f) ? (v2 + 1.f) : __expf(v2);
            v3 = (v3 > 0.f) ? (v3 + 1.f) : __expf(v3);
            *(float2*)&g_qk[(size_t)row0 * 1024 + col]       = make_float2(v0, v1);
            *(float2*)&g_qk[(size_t)(row0 + 8) * 1024 + col] = make_float2(v2, v3);
        }
    }
}

// ============================================================
// K2: kmean[b, c] = mean_n k_post[b, n, c]
// ============================================================
__global__ void kmean_kernel() {
    const int b   = blockIdx.y;
    const int col = blockIdx.x * 128 + threadIdx.x;
    float s = 0.f;
#pragma unroll 8
    for (int n = 0; n < N_; n++)
        s += g_qk[((size_t)(b * N_ + n)) * CK_ + C_ + col];
    g_kmean[b * C_ + col] = s * (1.0f / N_);
}

// ============================================================
// K3: split-K partial kv
// ============================================================
__global__ __launch_bounds__(256)
void kv_partial_kernel(const float* __restrict__ X) {
    const int split = blockIdx.x, h = blockIdx.y, b = blockIdx.z;
    __shared__ float ks[16][64];
    __shared__ float vs[16][64];

    const int tid = threadIdx.x;
    const int ty = tid >> 4, tx = tid & 15;
    const int n0 = split * (N_ / SPLITS);

    float acc[4][4];
#pragma unroll
    for (int i = 0; i < 4; i++)
#pragma unroll
        for (int j = 0; j < 4; j++) acc[i][j] = 0.f;

    for (int c0 = 0; c0 < N_ / SPLITS; c0 += 16) {
#pragma unroll
        for (int l = 0; l < 2; l++) {
            const int p   = tid + l * 256;
            const int row = p >> 5, kd = p & 31;
            const int n   = n0 + c0 + row;
            const float2 kq = *(const float2*)&g_qk[((size_t)(b * N_ + n)) * CK_ + C_ + h * D_ + 2 * kd];
            const int ci = n * 256 + h * 32 + kd;
            const float cc = g_cos[ci], ss = g_sin[ci];
            float2 kr;
            kr.x = kq.x * cc - kq.y * ss;
            kr.y = kq.x * ss + kq.y * cc;
            *(float2*)&ks[row][2 * kd] = kr;
        }
        {
            const int row = tid >> 4;
            const int e4  = (tid & 15) * 4;
            const int n   = n0 + c0 + row;
            *(float4*)&vs[row][e4] =
                *(const float4*)&X[((size_t)(b * N_ + n)) * C_ + h * D_ + e4];
        }
        __syncthreads();

#pragma unroll
        for (int nn = 0; nn < 16; nn++) {
            float kr[4], vr[4];
#pragma unroll
            for (int i = 0; i < 4; i++) kr[i] = ks[nn][ty * 4 + i];
#pragma unroll
            for (int j = 0; j < 4; j++) vr[j] = vs[nn][tx * 4 + j];
#pragma unroll
            for (int i = 0; i < 4; i++)
#pragma unroll
                for (int j = 0; j < 4; j++) acc[i][j] += kr[i] * vr[j];
        }
        __syncthreads();
    }

    float* dst = &g_kvp[(((size_t)split * B_ + b) * H_ + h) * (D_ * D_)];
#pragma unroll
    for (int i = 0; i < 4; i++)
#pragma unroll
        for (int j = 0; j < 4; j++)
            dst[(ty * 4 + i) * D_ + tx * 4 + j] = acc[i][j];
}

// ============================================================
// K4: kv reduce
// ============================================================
__global__ void kv_reduce_kernel() {
    const int i = blockIdx.x * 256 + threadIdx.x;
    float s = 0.f;
#pragma unroll
    for (int sp = 0; sp < SPLITS; sp++)
        s += g_kvp[(size_t)sp * (B_ * H_ * D_ * D_) + i];
    g_kv[i] = s * (1.0f / N_);
}

// ============================================================
// K5: finalize: out = (q_rope @ kv) * z + lepe
// ============================================================
__global__ __launch_bounds__(256)
void finalize_kernel(const float* __restrict__ X, const float* __restrict__ LW,
                     const float* __restrict__ LB, float* __restrict__ out) {
    const int hp = blockIdx.x;
    const int h  = blockIdx.y;
    const int b  = blockIdx.z;

    __shared__ float kvs[64][64];
    __shared__ float qs[64][64];
    __shared__ float zs[64];
    __shared__ float km[64];
    __shared__ float w9s[9][64];

    const int tid = threadIdx.x;

    {
        const float* kvsrc = &g_kv[((size_t)(b * H_ + h)) * (D_ * D_)];
        for (int i = tid; i < 1024; i += 256)
            ((float4*)kvs)[i] = ((const float4*)kvsrc)[i];
    }
    if (tid < 64) km[tid] = g_kmean[b * C_ + h * D_ + tid];
    for (int i = tid; i < 576; i += 256) {
        const int p = i / 64, e = i % 64;
        w9s[p][e] = LW[p * C_ + h * D_ + e];
    }
    __syncthreads();

    {
        const int w = tid >> 5, lane = tid & 31;
#pragma unroll
        for (int rr = 0; rr < 8; rr++) {
            const int r = w * 8 + rr;
            const int n = hp * 64 + r;
            const float2 qv = *(const float2*)&g_qk[((size_t)(b * N_ + n)) * CK_ + h * D_ + 2 * lane];
            const int ci = n * 256 + h * 32 + lane;
            const float cc = g_cos[ci], ss = g_sin[ci];
            float2 qr;
            qr.x = qv.x * cc - qv.y * ss;
            qr.y = qv.x * ss + qv.y * cc;
            *(float2*)&qs[r][2 * lane] = qr;
            float zp = qv.x * km[2 * lane] + qv.y * km[2 * lane + 1];
#pragma unroll
            for (int o = 16; o > 0; o >>= 1) zp += __shfl_xor_sync(0xffffffffu, zp, o);
            if (lane == 0) zs[r] = 1.0f / (zp + 1e-6f);
        }
    }
    __syncthreads();

    const int e = tid & 63;
    const int c = h * D_ + e;
    const float lbias = LB[c];
    for (int r = tid >> 6; r < 64; r += 4) {
        float acc = 0.f;
#pragma unroll
        for (int d = 0; d < 64; d++) acc += qs[r][d] * kvs[d][e];

        float lep = lbias;
#pragma unroll
        for (int di = 0; di < 3; di++) {
            const int h2 = hp + di - 1;
            if ((unsigned)h2 < 64u) {
#pragma unroll
                for (int dj = 0; dj < 3; dj++) {
                    const int w2 = r + dj - 1;
                    if ((unsigned)w2 < 64u)
                        lep += X[((size_t)(b * N_ + h2 * 64 + w2)) * C_ + c] * w9s[di * 3 + dj][e];
                }
            }
        }
        out[((size_t)(b * N_ + hp * 64 + r)) * C_ + c] = acc * zs[r] + lep;
    }
}

// ============================================================
extern "C" void kernel_launch(void* const* d_in, const int* in_sizes, int n_in,
                              void* d_out, int out_size) {
    (void)in_sizes; (void)n_in; (void)out_size;
    const float* x  = (const float*)d_in[0];   // (16, 4096, 512)
    const float* W  = (const float*)d_in[1];   // (512, 1024)
    const float* qb = (const float*)d_in[2];   // (1024,)
    const float* lw = (const float*)d_in[3];   // (3,3,1,512)
    const float* lb = (const float*)d_in[4];   // (512,)
    float* out = (float*)d_out;                // (16, 4096, 512)

    cudaFuncSetAttribute(qk_gemm_mma, cudaFuncAttributeMaxDynamicSharedMemorySize, GSMEM);

    rope_init_kernel<<<(N_ * 256 + 255) / 256, 256>>>();
    convert_x_kernel<<<(int)(((size_t)B_ * N_ * C_ / 4) / 256), 256>>>(x);
    convert_w_kernel<<<(C_ * CK_) / 256, 256>>>(W);
    qk_gemm_mma<<<dim3(CK_ / 128, (B_ * N_) / 128), 256, GSMEM>>>(qb);
    kmean_kernel<<<dim3(C_ / 128, B_), 128>>>();
    kv_partial_kernel<<<dim3(SPLITS, H_, B_), 256>>>(x);
    kv_reduce_kernel<<<(B_ * H_ * D_ * D_) / 256, 256>>>();
    finalize_kernel<<<dim3(64, H_, B_), 256>>>(x, lw, lb, out);
}

// round 5
// speedup vs baseline: 2.0592x; 1.4209x over previous
#include <cuda_runtime.h>
#include <cuda_bf16.h>
#include <cstdint>
#include <math.h>

#define B_  16
#define N_  4096
#define C_  512
#define H_  8
#define D_  64
#define CK_ 1024
#define SPLITS 16

// -------- scratch (device globals; no runtime allocation) --------
__device__ float g_qk[(size_t)B_ * N_ * CK_];        // elu(q)+1 | elu(k)+1, (b,n,1024)
__device__ float g_cos[N_ * 256];
__device__ float g_sin[N_ * 256];
__device__ float g_kmean[B_ * C_];
__device__ float g_kpart[SPLITS][B_][C_];
__device__ float g_kvp[SPLITS * B_ * H_ * D_ * D_];
__device__ float g_kv[B_ * H_ * D_ * D_];
// bf16 hi/lo split operands
__device__ __nv_bfloat16 g_Ahi[(size_t)B_ * N_ * C_];   // [65536][512]
__device__ __nv_bfloat16 g_Alo[(size_t)B_ * N_ * C_];
__device__ __nv_bfloat16 g_Whi[CK_ * C_];               // transposed: [1024][512] K-major
__device__ __nv_bfloat16 g_Wlo[CK_ * C_];

// ============ PTX helpers (plain sm_103-safe: mma.sync / ldmatrix / cp.async) ============
__device__ __forceinline__ uint32_t smem_u32(const void* p) {
    uint32_t a;
    asm("{ .reg .u64 t; cvta.to.shared.u64 t, %1; cvt.u32.u64 %0, t; }" : "=r"(a) : "l"(p));
    return a;
}
__device__ __forceinline__ void cp16(uint32_t dst, const void* src) {
    asm volatile("cp.async.cg.shared.global [%0], [%1], 16;" :: "r"(dst), "l"(src) : "memory");
}
#define CP_COMMIT() asm volatile("cp.async.commit_group;" ::: "memory")
#define CP_WAIT(n)  asm volatile("cp.async.wait_group %0;" :: "n"(n) : "memory")

__device__ __forceinline__ void ldsm_x4(uint32_t (&r)[4], uint32_t addr) {
    asm volatile("ldmatrix.sync.aligned.m8n8.x4.shared.b16 {%0,%1,%2,%3}, [%4];"
                 : "=r"(r[0]), "=r"(r[1]), "=r"(r[2]), "=r"(r[3]) : "r"(addr));
}
__device__ __forceinline__ void mma16816(float (&c)[4], const uint32_t (&a)[4],
                                         uint32_t b0, uint32_t b1) {
    asm volatile(
        "mma.sync.aligned.m16n8k16.row.col.f32.bf16.bf16.f32 "
        "{%0,%1,%2,%3}, {%4,%5,%6,%7}, {%8,%9}, {%0,%1,%2,%3};"
        : "+f"(c[0]), "+f"(c[1]), "+f"(c[2]), "+f"(c[3])
        : "r"(a[0]), "r"(a[1]), "r"(a[2]), "r"(a[3]), "r"(b0), "r"(b1));
}

// ============================================================
// K0: RoPE cos/sin table.
// ============================================================
__global__ void rope_init_kernel() {
    int idx = blockIdx.x * blockDim.x + threadIdx.x;
    if (idx >= N_ * 256) return;
    int n  = idx >> 8;
    int k  = idx & 255;
    int hp = n >> 6, wp = n & 63;
    int kk = k & 127;
    float pos   = (k < 128) ? (float)hp : (float)wp;
    float theta = powf(10000.0f, -(float)kk / 128.0f);
    float a = pos * theta;
    g_cos[idx] = cosf(a);
    g_sin[idx] = sinf(a);
}

// ============================================================
// converts: fp32 -> bf16 hi/lo
// ============================================================
__global__ void convert_x_kernel(const float* __restrict__ X) {
    size_t i = ((size_t)blockIdx.x * 256 + threadIdx.x) * 4;
    float4 v = *(const float4*)(X + i);
    __nv_bfloat16 hv[4], lv[4];
    float f[4] = {v.x, v.y, v.z, v.w};
#pragma unroll
    for (int j = 0; j < 4; j++) {
        hv[j] = __float2bfloat16(f[j]);
        lv[j] = __float2bfloat16(f[j] - __bfloat162float(hv[j]));
    }
    *(uint2*)(g_Ahi + i) = *(uint2*)hv;
    *(uint2*)(g_Alo + i) = *(uint2*)lv;
}

__global__ void convert_w_kernel(const float* __restrict__ W) {
    int i = blockIdx.x * 256 + threadIdx.x;   // over 512*1024
    int k = i >> 10, n = i & 1023;
    float v = W[i];
    __nv_bfloat16 h = __float2bfloat16(v);
    __nv_bfloat16 l = __float2bfloat16(v - __bfloat162float(h));
    g_Whi[n * 512 + k] = h;
    g_Wlo[n * 512 + k] = l;
}

// ============================================================
// K1: mma.sync bf16x3 GEMM (unchanged from R4 — proven)
// ============================================================
#define BK      32
#define ROWB    80
#define BUF_SZ  (128 * ROWB)
#define STG_SZ  (4 * BUF_SZ)
#define GSMEM   (2 * STG_SZ)

__global__ __launch_bounds__(256, 2)
void qk_gemm_mma(const float* __restrict__ bias) {
    extern __shared__ char smem[];
    const uint32_t sb = smem_u32(smem);

    const int tid  = threadIdx.x;
    const int warp = tid >> 5, lane = tid & 31;
    const int wm = warp & 3;
    const int wn = warp >> 2;
    const int n0 = blockIdx.x * 128;
    const int m0 = blockIdx.y * 128;

    const int c0r = tid >> 2,            c0c = (tid & 3);
    const int c1r = (tid + 256) >> 2,    c1c = c0c;

    float acc[2][8][4];
#pragma unroll
    for (int a = 0; a < 2; a++)
#pragma unroll
        for (int b = 0; b < 8; b++)
#pragma unroll
            for (int c = 0; c < 4; c++) acc[a][b][c] = 0.f;

    auto prefetch = [&](int s, int k0) {
        const uint32_t st = sb + s * STG_SZ;
        const size_t gA0 = (size_t)(m0 + c0r) * 512 + k0 + c0c * 8;
        const size_t gA1 = (size_t)(m0 + c1r) * 512 + k0 + c1c * 8;
        const size_t gB0 = (size_t)(n0 + c0r) * 512 + k0 + c0c * 8;
        const size_t gB1 = (size_t)(n0 + c1r) * 512 + k0 + c1c * 8;
        const uint32_t s0 = c0r * ROWB + c0c * 16;
        const uint32_t s1 = c1r * ROWB + c1c * 16;
        cp16(st + 0 * BUF_SZ + s0, g_Ahi + gA0);
        cp16(st + 0 * BUF_SZ + s1, g_Ahi + gA1);
        cp16(st + 1 * BUF_SZ + s0, g_Alo + gA0);
        cp16(st + 1 * BUF_SZ + s1, g_Alo + gA1);
        cp16(st + 2 * BUF_SZ + s0, g_Whi + gB0);
        cp16(st + 2 * BUF_SZ + s1, g_Whi + gB1);
        cp16(st + 3 * BUF_SZ + s0, g_Wlo + gB0);
        cp16(st + 3 * BUF_SZ + s1, g_Wlo + gB1);
    };

    prefetch(0, 0);
    CP_COMMIT();

    const uint32_t aoff = (wm * 32 + (lane & 15)) * ROWB + (lane >> 4) * 16;
    const uint32_t boff = (wn * 64 + (lane & 15)) * ROWB + (lane >> 4) * 16;

#pragma unroll 1
    for (int ks = 0; ks < 16; ks++) {
        if (ks < 15) { prefetch((ks + 1) & 1, (ks + 1) * BK); CP_COMMIT(); CP_WAIT(1); }
        else         { CP_WAIT(0); }
        __syncthreads();

        const uint32_t st = sb + (ks & 1) * STG_SZ;
#pragma unroll
        for (int kk = 0; kk < 2; kk++) {
            const uint32_t kb = kk * 32;
            uint32_t ah[2][4], al[2][4], bh[4][4], bl[4][4];
#pragma unroll
            for (int mt = 0; mt < 2; mt++) {
                ldsm_x4(ah[mt], st + 0 * BUF_SZ + aoff + mt * (16 * ROWB) + kb);
                ldsm_x4(al[mt], st + 1 * BUF_SZ + aoff + mt * (16 * ROWB) + kb);
            }
#pragma unroll
            for (int nt = 0; nt < 4; nt++) {
                ldsm_x4(bh[nt], st + 2 * BUF_SZ + boff + nt * (16 * ROWB) + kb);
                ldsm_x4(bl[nt], st + 3 * BUF_SZ + boff + nt * (16 * ROWB) + kb);
            }
#pragma unroll
            for (int mt = 0; mt < 2; mt++) {
#pragma unroll
                for (int nt = 0; nt < 4; nt++) {
                    mma16816(acc[mt][2 * nt + 0], ah[mt], bh[nt][0], bh[nt][2]);
                    mma16816(acc[mt][2 * nt + 1], ah[mt], bh[nt][1], bh[nt][3]);
                    mma16816(acc[mt][2 * nt + 0], ah[mt], bl[nt][0], bl[nt][2]);
                    mma16816(acc[mt][2 * nt + 1], ah[mt], bl[nt][1], bl[nt][3]);
                    mma16816(acc[mt][2 * nt + 0], al[mt], bh[nt][0], bh[nt][2]);
                    mma16816(acc[mt][2 * nt + 1], al[mt], bh[nt][1], bh[nt][3]);
                }
            }
        }
        __syncthreads();
    }

#pragma unroll
    for (int mt = 0; mt < 2; mt++) {
        const int row0 = m0 + wm * 32 + mt * 16 + (lane >> 2);
#pragma unroll
        for (int nt = 0; nt < 8; nt++) {
            const int col = n0 + wn * 64 + nt * 8 + (lane & 3) * 2;
            const float b0 = __ldg(&bias[col]);
            const float b1 = __ldg(&bias[col + 1]);
            float v0 = acc[mt][nt][0] + b0;
            float v1 = acc[mt][nt][1] + b1;
            float v2 = acc[mt][nt][2] + b0;
            float v3 = acc[mt][nt][3] + b1;
            v0 = (v0 > 0.f) ? (v0 + 1.f) : __expf(v0);
            v1 = (v1 > 0.f) ? (v1 + 1.f) : __expf(v1);
            v2 = (v2 > 0.f) ? (v2 + 1.f) : __expf(v2);
            v3 = (v3 > 0.f) ? (v3 + 1.f) : __expf(v3);
            *(float2*)&g_qk[(size_t)row0 * 1024 + col]       = make_float2(v0, v1);
            *(float2*)&g_qk[(size_t)(row0 + 8) * 1024 + col] = make_float2(v2, v3);
        }
    }
}

// ============================================================
// K2a/K2b: kmean 2-stage tree reduction
// ============================================================
__global__ __launch_bounds__(512)
void kmean_stage1() {
    const int split = blockIdx.x, b = blockIdx.y;
    const int col = threadIdx.x;                 // 0..511
    const int n0 = split * (N_ / SPLITS);
    float s = 0.f;
#pragma unroll 8
    for (int n = 0; n < N_ / SPLITS; n++)
        s += g_qk[((size_t)(b * N_ + n0 + n)) * CK_ + C_ + col];
    g_kpart[split][b][col] = s;
}

__global__ __launch_bounds__(512)
void kmean_stage2() {
    const int b = blockIdx.x;
    const int col = threadIdx.x;
    float s = 0.f;
#pragma unroll
    for (int sp = 0; sp < SPLITS; sp++)
        s += g_kpart[sp][b][col];
    g_kmean[b * C_ + col] = s * (1.0f / N_);
}

// ============================================================
// K3: split-K partial kv (unchanged)
// ============================================================
__global__ __launch_bounds__(256)
void kv_partial_kernel(const float* __restrict__ X) {
    const int split = blockIdx.x, h = blockIdx.y, b = blockIdx.z;
    __shared__ float ks[16][64];
    __shared__ float vs[16][64];

    const int tid = threadIdx.x;
    const int ty = tid >> 4, tx = tid & 15;
    const int n0 = split * (N_ / SPLITS);

    float acc[4][4];
#pragma unroll
    for (int i = 0; i < 4; i++)
#pragma unroll
        for (int j = 0; j < 4; j++) acc[i][j] = 0.f;

    for (int c0 = 0; c0 < N_ / SPLITS; c0 += 16) {
#pragma unroll
        for (int l = 0; l < 2; l++) {
            const int p   = tid + l * 256;
            const int row = p >> 5, kd = p & 31;
            const int n   = n0 + c0 + row;
            const float2 kq = *(const float2*)&g_qk[((size_t)(b * N_ + n)) * CK_ + C_ + h * D_ + 2 * kd];
            const int ci = n * 256 + h * 32 + kd;
            const float cc = g_cos[ci], ss = g_sin[ci];
            float2 kr;
            kr.x = kq.x * cc - kq.y * ss;
            kr.y = kq.x * ss + kq.y * cc;
            *(float2*)&ks[row][2 * kd] = kr;
        }
        {
            const int row = tid >> 4;
            const int e4  = (tid & 15) * 4;
            const int n   = n0 + c0 + row;
            *(float4*)&vs[row][e4] =
                *(const float4*)&X[((size_t)(b * N_ + n)) * C_ + h * D_ + e4];
        }
        __syncthreads();

#pragma unroll
        for (int nn = 0; nn < 16; nn++) {
            float kr[4], vr[4];
#pragma unroll
            for (int i = 0; i < 4; i++) kr[i] = ks[nn][ty * 4 + i];
#pragma unroll
            for (int j = 0; j < 4; j++) vr[j] = vs[nn][tx * 4 + j];
#pragma unroll
            for (int i = 0; i < 4; i++)
#pragma unroll
                for (int j = 0; j < 4; j++) acc[i][j] += kr[i] * vr[j];
        }
        __syncthreads();
    }

    float* dst = &g_kvp[(((size_t)split * B_ + b) * H_ + h) * (D_ * D_)];
#pragma unroll
    for (int i = 0; i < 4; i++)
#pragma unroll
        for (int j = 0; j < 4; j++)
            dst[(ty * 4 + i) * D_ + tx * 4 + j] = acc[i][j];
}

// ============================================================
// K4: kv reduce
// ============================================================
__global__ void kv_reduce_kernel() {
    const int i = blockIdx.x * 256 + threadIdx.x;
    float s = 0.f;
#pragma unroll
    for (int sp = 0; sp < SPLITS; sp++)
        s += g_kvp[(size_t)sp * (B_ * H_ * D_ * D_) + i];
    g_kv[i] = s * (1.0f / N_);
}

// ============================================================
// K5: finalize: out = (q_rope @ kv) * z + lepe, with smem X halo tile
// dynamic smem layout (floats):
//   kvs[4096] | qs[4096] | xt[3*64*64=12288] | w9s[576] | zs[64] | km[64]
// ============================================================
#define FSM_FLOATS (4096 + 4096 + 12288 + 576 + 64 + 64)

__global__ __launch_bounds__(256)
void finalize_kernel(const float* __restrict__ X, const float* __restrict__ LW,
                     const float* __restrict__ LB, float* __restrict__ out) {
    extern __shared__ float fsm[];
    float* kvs = fsm;              // [64][64]
    float* qs  = kvs + 4096;       // [64][64]
    float* xt  = qs + 4096;        // [3][64][64]
    float* w9s = xt + 12288;       // [9][64]
    float* zs  = w9s + 576;        // [64]
    float* km  = zs + 64;          // [64]

    const int hp = blockIdx.x;
    const int h  = blockIdx.y;
    const int b  = blockIdx.z;
    const int tid = threadIdx.x;

    // phase 1: load kv tile, km, conv weights, X halo tile
    {
        const float* kvsrc = &g_kv[((size_t)(b * H_ + h)) * (D_ * D_)];
        for (int i = tid; i < 1024; i += 256)
            ((float4*)kvs)[i] = ((const float4*)kvsrc)[i];
    }
    if (tid < 64) km[tid] = g_kmean[b * C_ + h * D_ + tid];
    for (int i = tid; i < 576; i += 256) {
        const int p = i / 64, e = i % 64;
        w9s[i] = LW[p * C_ + h * D_ + e];
    }
    for (int i = tid; i < 12288; i += 256) {
        const int di = i >> 12;
        const int rem = i & 4095;
        const int w = rem >> 6, e = rem & 63;
        const int h2 = hp + di - 1;
        float v = 0.f;
        if ((unsigned)h2 < 64u)
            v = X[((size_t)(b * N_ + h2 * 64 + w)) * C_ + h * D_ + e];
        xt[i] = v;
    }
    __syncthreads();

    // phase 2: q-RoPE + z
    {
        const int w = tid >> 5, lane = tid & 31;
#pragma unroll
        for (int rr = 0; rr < 8; rr++) {
            const int r = w * 8 + rr;
            const int n = hp * 64 + r;
            const float2 qv = *(const float2*)&g_qk[((size_t)(b * N_ + n)) * CK_ + h * D_ + 2 * lane];
            const int ci = n * 256 + h * 32 + lane;
            const float cc = g_cos[ci], ss = g_sin[ci];
            float2 qr;
            qr.x = qv.x * cc - qv.y * ss;
            qr.y = qv.x * ss + qv.y * cc;
            *(float2*)&qs[r * 64 + 2 * lane] = qr;
            float zp = qv.x * km[2 * lane] + qv.y * km[2 * lane + 1];
#pragma unroll
            for (int o = 16; o > 0; o >>= 1) zp += __shfl_xor_sync(0xffffffffu, zp, o);
            if (lane == 0) zs[r] = 1.0f / (zp + 1e-6f);
        }
    }
    __syncthreads();

    // phase 3: matvec + lepe from smem
    const int e = tid & 63;
    const int c = h * D_ + e;
    const float lbias = LB[c];
    for (int r = tid >> 6; r < 64; r += 4) {
        float acc = 0.f;
#pragma unroll
        for (int d = 0; d < 64; d++) acc += qs[r * 64 + d] * kvs[d * 64 + e];

        float lep = lbias;
#pragma unroll
        for (int di = 0; di < 3; di++) {
#pragma unroll
            for (int dj = 0; dj < 3; dj++) {
                const int w2 = r + dj - 1;
                if ((unsigned)w2 < 64u)
                    lep += xt[di * 4096 + w2 * 64 + e] * w9s[(di * 3 + dj) * 64 + e];
            }
        }
        out[((size_t)(b * N_ + hp * 64 + r)) * C_ + c] = acc * zs[r] + lep;
    }
}

// ============================================================
extern "C" void kernel_launch(void* const* d_in, const int* in_sizes, int n_in,
                              void* d_out, int out_size) {
    (void)in_sizes; (void)n_in; (void)out_size;
    const float* x  = (const float*)d_in[0];   // (16, 4096, 512)
    const float* W  = (const float*)d_in[1];   // (512, 1024)
    const float* qb = (const float*)d_in[2];   // (1024,)
    const float* lw = (const float*)d_in[3];   // (3,3,1,512)
    const float* lb = (const float*)d_in[4];   // (512,)
    float* out = (float*)d_out;                // (16, 4096, 512)

    cudaFuncSetAttribute(qk_gemm_mma, cudaFuncAttributeMaxDynamicSharedMemorySize, GSMEM);
    cudaFuncSetAttribute(finalize_kernel, cudaFuncAttributeMaxDynamicSharedMemorySize,
                         FSM_FLOATS * 4);

    rope_init_kernel<<<(N_ * 256 + 255) / 256, 256>>>();
    convert_x_kernel<<<(int)(((size_t)B_ * N_ * C_ / 4) / 256), 256>>>(x);
    convert_w_kernel<<<(C_ * CK_) / 256, 256>>>(W);
    qk_gemm_mma<<<dim3(CK_ / 128, (B_ * N_) / 128), 256, GSMEM>>>(qb);
    kmean_stage1<<<dim3(SPLITS, B_), 512>>>();
    kmean_stage2<<<B_, 512>>>();
    kv_partial_kernel<<<dim3(SPLITS, H_, B_), 256>>>(x);
    kv_reduce_kernel<<<(B_ * H_ * D_ * D_) / 256, 256>>>();
    finalize_kernel<<<dim3(64, H_, B_), 256, FSM_FLOATS * 4>>>(x, lw, lb, out);
}

// round 6
// speedup vs baseline: 2.6822x; 1.3025x over previous
#include <cuda_runtime.h>
#include <cuda_bf16.h>
#include <cuda_fp16.h>
#include <cstdint>
#include <math.h>

#define B_  16
#define N_  4096
#define C_  512
#define H_  8
#define D_  64
#define CK_ 1024
#define SPLITS 16

// -------- scratch (device globals; no runtime allocation) --------
__device__ float g_qk[(size_t)B_ * N_ * CK_];        // elu(q)+1 | elu(k)+1, (b,n,1024)
__device__ float g_cos[N_ * 256];
__device__ float g_sin[N_ * 256];
__device__ float g_kmean[B_ * C_];
__device__ float g_kpart[SPLITS][B_][C_];
__device__ float g_kvp[SPLITS * B_ * H_ * D_ * D_];
__device__ float g_kv[B_ * H_ * D_ * D_];
// fp16 GEMM operands
__device__ __half g_Af16[(size_t)B_ * N_ * C_];   // [65536][512]
__device__ __half g_Wf16[CK_ * C_];               // transposed: [1024][512] K-major

// ============ PTX helpers (plain sm_103-safe) ============
__device__ __forceinline__ uint32_t smem_u32(const void* p) {
    uint32_t a;
    asm("{ .reg .u64 t; cvta.to.shared.u64 t, %1; cvt.u32.u64 %0, t; }" : "=r"(a) : "l"(p));
    return a;
}
__device__ __forceinline__ void cp16(uint32_t dst, const void* src) {
    asm volatile("cp.async.cg.shared.global [%0], [%1], 16;" :: "r"(dst), "l"(src) : "memory");
}
#define CP_COMMIT() asm volatile("cp.async.commit_group;" ::: "memory")
#define CP_WAIT(n)  asm volatile("cp.async.wait_group %0;" :: "n"(n) : "memory")

__device__ __forceinline__ void ldsm_x4(uint32_t (&r)[4], uint32_t addr) {
    asm volatile("ldmatrix.sync.aligned.m8n8.x4.shared.b16 {%0,%1,%2,%3}, [%4];"
                 : "=r"(r[0]), "=r"(r[1]), "=r"(r[2]), "=r"(r[3]) : "r"(addr));
}
__device__ __forceinline__ void mma16816(float (&c)[4], const uint32_t (&a)[4],
                                         uint32_t b0, uint32_t b1) {
    asm volatile(
        "mma.sync.aligned.m16n8k16.row.col.f32.f16.f16.f32 "
        "{%0,%1,%2,%3}, {%4,%5,%6,%7}, {%8,%9}, {%0,%1,%2,%3};"
        : "+f"(c[0]), "+f"(c[1]), "+f"(c[2]), "+f"(c[3])
        : "r"(a[0]), "r"(a[1]), "r"(a[2]), "r"(a[3]), "r"(b0), "r"(b1));
}

// ============================================================
// K0: RoPE cos/sin table.
// ============================================================
__global__ void rope_init_kernel() {
    int idx = blockIdx.x * blockDim.x + threadIdx.x;
    if (idx >= N_ * 256) return;
    int n  = idx >> 8;
    int k  = idx & 255;
    int hp = n >> 6, wp = n & 63;
    int kk = k & 127;
    float pos   = (k < 128) ? (float)hp : (float)wp;
    float theta = powf(10000.0f, -(float)kk / 128.0f);
    float a = pos * theta;
    g_cos[idx] = cosf(a);
    g_sin[idx] = sinf(a);
}

// ============================================================
// converts: fp32 -> fp16
// ============================================================
__global__ void convert_x_kernel(const float* __restrict__ X) {
    size_t i = ((size_t)blockIdx.x * 256 + threadIdx.x) * 4;
    float4 v = *(const float4*)(X + i);
    __half hv[4];
    hv[0] = __float2half_rn(v.x);
    hv[1] = __float2half_rn(v.y);
    hv[2] = __float2half_rn(v.z);
    hv[3] = __float2half_rn(v.w);
    *(uint2*)(g_Af16 + i) = *(uint2*)hv;
}

__global__ void convert_w_kernel(const float* __restrict__ W) {
    int i = blockIdx.x * 256 + threadIdx.x;   // over 512*1024
    int k = i >> 10, n = i & 1023;
    g_Wf16[n * 512 + k] = __float2half_rn(W[i]);
}

// ============================================================
// K1: mma.sync fp16 single-pass GEMM: g_qk = elu(X @ W + bias) + 1
//     CTA tile 128x128, BK=32, 8 warps (32x64 each),
//     3-stage cp.async pipeline, one sync/iter, 80B-padded rows.
// ============================================================
#define BK      32
#define ROWB    80
#define BUF_SZ  (128 * ROWB)      // 10240 bytes (one operand tile)
#define STG_SZ  (2 * BUF_SZ)      // A + B = 20480
#define NSTG    3
#define GSMEM   (NSTG * STG_SZ)   // 61440

__global__ __launch_bounds__(256, 2)
void qk_gemm_mma(const float* __restrict__ bias) {
    extern __shared__ char smem[];
    const uint32_t sb = smem_u32(smem);

    const int tid  = threadIdx.x;
    const int warp = tid >> 5, lane = tid & 31;
    const int wm = warp & 3;
    const int wn = warp >> 2;
    const int n0 = blockIdx.x * 128;
    const int m0 = blockIdx.y * 128;

    float acc[2][8][4];
#pragma unroll
    for (int a = 0; a < 2; a++)
#pragma unroll
        for (int b = 0; b < 8; b++)
#pragma unroll
            for (int c = 0; c < 4; c++) acc[a][b][c] = 0.f;

    auto prefetch = [&](int s, int k0) {
        const uint32_t st = sb + s * STG_SZ;
#pragma unroll
        for (int it = 0; it < 2; it++) {
            const int u   = tid + it * 256;      // 0..511
            const int row = u >> 2, c = u & 3;
            const uint32_t so = row * ROWB + c * 16;
            cp16(st + so,          g_Af16 + (size_t)(m0 + row) * 512 + k0 + c * 8);
            cp16(st + BUF_SZ + so, g_Wf16 + (size_t)(n0 + row) * 512 + k0 + c * 8);
        }
    };

    prefetch(0, 0); CP_COMMIT();
    prefetch(1, BK); CP_COMMIT();

    const uint32_t aoff = (wm * 32 + (lane & 15)) * ROWB + (lane >> 4) * 16;
    const uint32_t boff = (wn * 64 + (lane & 15)) * ROWB + (lane >> 4) * 16;

#pragma unroll 1
    for (int ks = 0; ks < 16; ks++) {
        if (ks < 15) { CP_WAIT(1); } else { CP_WAIT(0); }
        __syncthreads();
        if (ks + 2 < 16) { prefetch((ks + 2) % NSTG, (ks + 2) * BK); CP_COMMIT(); }

        const uint32_t st = sb + (ks % NSTG) * STG_SZ;
#pragma unroll
        for (int kk = 0; kk < 2; kk++) {
            const uint32_t kb = kk * 32;
            uint32_t ah[2][4], bh[4][4];
#pragma unroll
            for (int mt = 0; mt < 2; mt++)
                ldsm_x4(ah[mt], st + aoff + mt * (16 * ROWB) + kb);
#pragma unroll
            for (int nt = 0; nt < 4; nt++)
                ldsm_x4(bh[nt], st + BUF_SZ + boff + nt * (16 * ROWB) + kb);
#pragma unroll
            for (int mt = 0; mt < 2; mt++) {
#pragma unroll
                for (int nt = 0; nt < 4; nt++) {
                    mma16816(acc[mt][2 * nt + 0], ah[mt], bh[nt][0], bh[nt][2]);
                    mma16816(acc[mt][2 * nt + 1], ah[mt], bh[nt][1], bh[nt][3]);
                }
            }
        }
        __syncthreads();
    }

#pragma unroll
    for (int mt = 0; mt < 2; mt++) {
        const int row0 = m0 + wm * 32 + mt * 16 + (lane >> 2);
#pragma unroll
        for (int nt = 0; nt < 8; nt++) {
            const int col = n0 + wn * 64 + nt * 8 + (lane & 3) * 2;
            const float b0 = __ldg(&bias[col]);
            const float b1 = __ldg(&bias[col + 1]);
            float v0 = acc[mt][nt][0] + b0;
            float v1 = acc[mt][nt][1] + b1;
            float v2 = acc[mt][nt][2] + b0;
            float v3 = acc[mt][nt][3] + b1;
            v0 = (v0 > 0.f) ? (v0 + 1.f) : __expf(v0);
            v1 = (v1 > 0.f) ? (v1 + 1.f) : __expf(v1);
            v2 = (v2 > 0.f) ? (v2 + 1.f) : __expf(v2);
            v3 = (v3 > 0.f) ? (v3 + 1.f) : __expf(v3);
            *(float2*)&g_qk[(size_t)row0 * 1024 + col]       = make_float2(v0, v1);
            *(float2*)&g_qk[(size_t)(row0 + 8) * 1024 + col] = make_float2(v2, v3);
        }
    }
}

// ============================================================
// K2a/K2b: kmean 2-stage tree reduction
// ============================================================
__global__ __launch_bounds__(512)
void kmean_stage1() {
    const int split = blockIdx.x, b = blockIdx.y;
    const int col = threadIdx.x;
    const int n0 = split * (N_ / SPLITS);
    float s = 0.f;
#pragma unroll 8
    for (int n = 0; n < N_ / SPLITS; n++)
        s += g_qk[((size_t)(b * N_ + n0 + n)) * CK_ + C_ + col];
    g_kpart[split][b][col] = s;
}

__global__ __launch_bounds__(512)
void kmean_stage2() {
    const int b = blockIdx.x;
    const int col = threadIdx.x;
    float s = 0.f;
#pragma unroll
    for (int sp = 0; sp < SPLITS; sp++)
        s += g_kpart[sp][b][col];
    g_kmean[b * C_ + col] = s * (1.0f / N_);
}

// ============================================================
// K3: split-K partial kv (32-row tiles)
// ============================================================
__global__ __launch_bounds__(256)
void kv_partial_kernel(const float* __restrict__ X) {
    const int split = blockIdx.x, h = blockIdx.y, b = blockIdx.z;
    __shared__ float ks[32][64];
    __shared__ float vs[32][64];

    const int tid = threadIdx.x;
    const int ty = tid >> 4, tx = tid & 15;
    const int n0 = split * (N_ / SPLITS);

    float acc[4][4];
#pragma unroll
    for (int i = 0; i < 4; i++)
#pragma unroll
        for (int j = 0; j < 4; j++) acc[i][j] = 0.f;

    for (int c0 = 0; c0 < N_ / SPLITS; c0 += 32) {
        // load + rotate K tile (32 rows x 32 pairs)
#pragma unroll
        for (int l = 0; l < 4; l++) {
            const int p   = tid + l * 256;        // 0..1023
            const int row = p >> 5, kd = p & 31;
            const int n   = n0 + c0 + row;
            const float2 kq = *(const float2*)&g_qk[((size_t)(b * N_ + n)) * CK_ + C_ + h * D_ + 2 * kd];
            const int ci = n * 256 + h * 32 + kd;
            const float cc = g_cos[ci], ss = g_sin[ci];
            float2 kr;
            kr.x = kq.x * cc - kq.y * ss;
            kr.y = kq.x * ss + kq.y * cc;
            *(float2*)&ks[row][2 * kd] = kr;
        }
        // load V tile (32 rows x 16 float4)
#pragma unroll
        for (int l = 0; l < 2; l++) {
            const int p   = tid + l * 256;        // 0..511
            const int row = p >> 4;
            const int e4  = (p & 15) * 4;
            const int n   = n0 + c0 + row;
            *(float4*)&vs[row][e4] =
                *(const float4*)&X[((size_t)(b * N_ + n)) * C_ + h * D_ + e4];
        }
        __syncthreads();

#pragma unroll
        for (int nn = 0; nn < 32; nn++) {
            float kr[4], vr[4];
#pragma unroll
            for (int i = 0; i < 4; i++) kr[i] = ks[nn][ty * 4 + i];
#pragma unroll
            for (int j = 0; j < 4; j++) vr[j] = vs[nn][tx * 4 + j];
#pragma unroll
            for (int i = 0; i < 4; i++)
#pragma unroll
                for (int j = 0; j < 4; j++) acc[i][j] += kr[i] * vr[j];
        }
        __syncthreads();
    }

    float* dst = &g_kvp[(((size_t)split * B_ + b) * H_ + h) * (D_ * D_)];
#pragma unroll
    for (int i = 0; i < 4; i++)
#pragma unroll
        for (int j = 0; j < 4; j++)
            dst[(ty * 4 + i) * D_ + tx * 4 + j] = acc[i][j];
}

// ============================================================
// K4: kv reduce
// ============================================================
__global__ void kv_reduce_kernel() {
    const int i = blockIdx.x * 256 + threadIdx.x;
    float s = 0.f;
#pragma unroll
    for (int sp = 0; sp < SPLITS; sp++)
        s += g_kvp[(size_t)sp * (B_ * H_ * D_ * D_) + i];
    g_kv[i] = s * (1.0f / N_);
}

// ============================================================
// K5: finalize: out = (q_rope @ kv) * z + lepe, smem X halo tile
// ============================================================
#define FSM_FLOATS (4096 + 4096 + 12288 + 576 + 64 + 64)

__global__ __launch_bounds__(256)
void finalize_kernel(const float* __restrict__ X, const float* __restrict__ LW,
                     const float* __restrict__ LB, float* __restrict__ out) {
    extern __shared__ float fsm[];
    float* kvs = fsm;
    float* qs  = kvs + 4096;
    float* xt  = qs + 4096;
    float* w9s = xt + 12288;
    float* zs  = w9s + 576;
    float* km  = zs + 64;

    const int hp = blockIdx.x;
    const int h  = blockIdx.y;
    const int b  = blockIdx.z;
    const int tid = threadIdx.x;

    {
        const float* kvsrc = &g_kv[((size_t)(b * H_ + h)) * (D_ * D_)];
        for (int i = tid; i < 1024; i += 256)
            ((float4*)kvs)[i] = ((const float4*)kvsrc)[i];
    }
    if (tid < 64) km[tid] = g_kmean[b * C_ + h * D_ + tid];
    for (int i = tid; i < 576; i += 256) {
        const int p = i / 64, e = i % 64;
        w9s[i] = LW[p * C_ + h * D_ + e];
    }
    for (int i = tid; i < 12288; i += 256) {
        const int di = i >> 12;
        const int rem = i & 4095;
        const int w = rem >> 6, e = rem & 63;
        const int h2 = hp + di - 1;
        float v = 0.f;
        if ((unsigned)h2 < 64u)
            v = X[((size_t)(b * N_ + h2 * 64 + w)) * C_ + h * D_ + e];
        xt[i] = v;
    }
    __syncthreads();

    {
        const int w = tid >> 5, lane = tid & 31;
#pragma unroll
        for (int rr = 0; rr < 8; rr++) {
            const int r = w * 8 + rr;
            const int n = hp * 64 + r;
            const float2 qv = *(const float2*)&g_qk[((size_t)(b * N_ + n)) * CK_ + h * D_ + 2 * lane];
            const int ci = n * 256 + h * 32 + lane;
            const float cc = g_cos[ci], ss = g_sin[ci];
            float2 qr;
            qr.x = qv.x * cc - qv.y * ss;
            qr.y = qv.x * ss + qv.y * cc;
            *(float2*)&qs[r * 64 + 2 * lane] = qr;
            float zp = qv.x * km[2 * lane] + qv.y * km[2 * lane + 1];
#pragma unroll
            for (int o = 16; o > 0; o >>= 1) zp += __shfl_xor_sync(0xffffffffu, zp, o);
            if (lane == 0) zs[r] = 1.0f / (zp + 1e-6f);
        }
    }
    __syncthreads();

    const int e = tid & 63;
    const int c = h * D_ + e;
    const float lbias = LB[c];
    for (int r = tid >> 6; r < 64; r += 4) {
        float acc = 0.f;
#pragma unroll
        for (int d = 0; d < 64; d++) acc += qs[r * 64 + d] * kvs[d * 64 + e];

        float lep = lbias;
#pragma unroll
        for (int di = 0; di < 3; di++) {
#pragma unroll
            for (int dj = 0; dj < 3; dj++) {
                const int w2 = r + dj - 1;
                if ((unsigned)w2 < 64u)
                    lep += xt[di * 4096 + w2 * 64 + e] * w9s[(di * 3 + dj) * 64 + e];
            }
        }
        out[((size_t)(b * N_ + hp * 64 + r)) * C_ + c] = acc * zs[r] + lep;
    }
}

// ============================================================
extern "C" void kernel_launch(void* const* d_in, const int* in_sizes, int n_in,
                              void* d_out, int out_size) {
    (void)in_sizes; (void)n_in; (void)out_size;
    const float* x  = (const float*)d_in[0];   // (16, 4096, 512)
    const float* W  = (const float*)d_in[1];   // (512, 1024)
    const float* qb = (const float*)d_in[2];   // (1024,)
    const float* lw = (const float*)d_in[3];   // (3,3,1,512)
    const float* lb = (const float*)d_in[4];   // (512,)
    float* out = (float*)d_out;                // (16, 4096, 512)

    cudaFuncSetAttribute(qk_gemm_mma, cudaFuncAttributeMaxDynamicSharedMemorySize, GSMEM);
    cudaFuncSetAttribute(finalize_kernel, cudaFuncAttributeMaxDynamicSharedMemorySize,
                         FSM_FLOATS * 4);

    rope_init_kernel<<<(N_ * 256 + 255) / 256, 256>>>();
    convert_x_kernel<<<(int)(((size_t)B_ * N_ * C_ / 4) / 256), 256>>>(x);
    convert_w_kernel<<<(C_ * CK_) / 256, 256>>>(W);
    qk_gemm_mma<<<dim3(CK_ / 128, (B_ * N_) / 128), 256, GSMEM>>>(qb);
    kmean_stage1<<<dim3(SPLITS, B_), 512>>>();
    kmean_stage2<<<B_, 512>>>();
    kv_partial_kernel<<<dim3(SPLITS, H_, B_), 256>>>(x);
    kv_reduce_kernel<<<(B_ * H_ * D_ * D_) / 256, 256>>>();
    finalize_kernel<<<dim3(64, H_, B_), 256, FSM_FLOATS * 4>>>(x, lw, lb, out);
}

// round 7
// speedup vs baseline: 2.7490x; 1.0249x over previous
#include <cuda_runtime.h>
#include <cuda_fp16.h>
#include <cstdint>
#include <math.h>

#define B_  16
#define N_  4096
#define C_  512
#define H_  8
#define D_  64
#define CK_ 1024
#define SPLITS 16

// -------- scratch (device globals; no runtime allocation) --------
__device__ __half g_qkh[(size_t)B_ * N_ * CK_];      // fp16: elu(q)+1 | elu(k)+1
__device__ float g_cos2[64 * 128];                   // [pos][kk]
__device__ float g_sin2[64 * 128];
__device__ float g_kmean[B_ * C_];
__device__ float g_kpart[SPLITS][B_][C_];
__device__ float g_kvp[SPLITS * B_ * H_ * D_ * D_];
__device__ float g_kv[B_ * H_ * D_ * D_];
__device__ __half g_Af16[(size_t)B_ * N_ * C_];      // x in fp16
__device__ __half g_Wf16[CK_ * C_];                  // W^T fp16, K-major

// ============ PTX helpers ============
__device__ __forceinline__ uint32_t smem_u32(const void* p) {
    uint32_t a;
    asm("{ .reg .u64 t; cvta.to.shared.u64 t, %1; cvt.u32.u64 %0, t; }" : "=r"(a) : "l"(p));
    return a;
}
__device__ __forceinline__ void cp16(uint32_t dst, const void* src) {
    asm volatile("cp.async.cg.shared.global [%0], [%1], 16;" :: "r"(dst), "l"(src) : "memory");
}
#define CP_COMMIT() asm volatile("cp.async.commit_group;" ::: "memory")
#define CP_WAIT(n)  asm volatile("cp.async.wait_group %0;" :: "n"(n) : "memory")

__device__ __forceinline__ void ldsm_x4(uint32_t (&r)[4], uint32_t addr) {
    asm volatile("ldmatrix.sync.aligned.m8n8.x4.shared.b16 {%0,%1,%2,%3}, [%4];"
                 : "=r"(r[0]), "=r"(r[1]), "=r"(r[2]), "=r"(r[3]) : "r"(addr));
}
__device__ __forceinline__ void mma16816(float (&c)[4], const uint32_t (&a)[4],
                                         uint32_t b0, uint32_t b1) {
    asm volatile(
        "mma.sync.aligned.m16n8k16.row.col.f32.f16.f16.f32 "
        "{%0,%1,%2,%3}, {%4,%5,%6,%7}, {%8,%9}, {%0,%1,%2,%3};"
        : "+f"(c[0]), "+f"(c[1]), "+f"(c[2]), "+f"(c[3])
        : "r"(a[0]), "r"(a[1]), "r"(a[2]), "r"(a[3]), "r"(b0), "r"(b1));
}

// ============================================================
// K0: compact RoPE table: angle(pos, kk) = pos * 10000^(-kk/128)
// ============================================================
__global__ void rope_init_kernel() {
    int idx = blockIdx.x * blockDim.x + threadIdx.x;   // < 8192
    int pos = idx >> 7, kk = idx & 127;
    float theta = powf(10000.0f, -(float)kk / 128.0f);
    float a = (float)pos * theta;
    g_cos2[idx] = cosf(a);
    g_sin2[idx] = sinf(a);
}

// ============================================================
// converts: fp32 -> fp16
// ============================================================
__global__ void convert_x_kernel(const float* __restrict__ X) {
    size_t i = ((size_t)blockIdx.x * 256 + threadIdx.x) * 4;
    float4 v = *(const float4*)(X + i);
    __half hv[4];
    hv[0] = __float2half_rn(v.x);
    hv[1] = __float2half_rn(v.y);
    hv[2] = __float2half_rn(v.z);
    hv[3] = __float2half_rn(v.w);
    *(uint2*)(g_Af16 + i) = *(uint2*)hv;
}

__global__ void convert_w_kernel(const float* __restrict__ W) {
    int i = blockIdx.x * 256 + threadIdx.x;   // over 512*1024
    int k = i >> 10, n = i & 1023;
    g_Wf16[n * 512 + k] = __float2half_rn(W[i]);
}

// ============================================================
// K1: fp16 mma GEMM: g_qkh = elu(X @ W + bias) + 1   (fp16 out)
// ============================================================
#define BK      32
#define ROWB    80
#define BUF_SZ  (128 * ROWB)
#define STG_SZ  (2 * BUF_SZ)
#define NSTG    3
#define GSMEM   (NSTG * STG_SZ)

__global__ __launch_bounds__(256, 2)
void qk_gemm_mma(const float* __restrict__ bias) {
    extern __shared__ char smem[];
    const uint32_t sb = smem_u32(smem);

    const int tid  = threadIdx.x;
    const int warp = tid >> 5, lane = tid & 31;
    const int wm = warp & 3;
    const int wn = warp >> 2;
    const int n0 = blockIdx.x * 128;
    const int m0 = blockIdx.y * 128;

    float acc[2][8][4];
#pragma unroll
    for (int a = 0; a < 2; a++)
#pragma unroll
        for (int b = 0; b < 8; b++)
#pragma unroll
            for (int c = 0; c < 4; c++) acc[a][b][c] = 0.f;

    auto prefetch = [&](int s, int k0) {
        const uint32_t st = sb + s * STG_SZ;
#pragma unroll
        for (int it = 0; it < 2; it++) {
            const int u   = tid + it * 256;
            const int row = u >> 2, c = u & 3;
            const uint32_t so = row * ROWB + c * 16;
            cp16(st + so,          g_Af16 + (size_t)(m0 + row) * 512 + k0 + c * 8);
            cp16(st + BUF_SZ + so, g_Wf16 + (size_t)(n0 + row) * 512 + k0 + c * 8);
        }
    };

    prefetch(0, 0); CP_COMMIT();
    prefetch(1, BK); CP_COMMIT();

    const uint32_t aoff = (wm * 32 + (lane & 15)) * ROWB + (lane >> 4) * 16;
    const uint32_t boff = (wn * 64 + (lane & 15)) * ROWB + (lane >> 4) * 16;

#pragma unroll 1
    for (int ks = 0; ks < 16; ks++) {
        if (ks < 15) { CP_WAIT(1); } else { CP_WAIT(0); }
        __syncthreads();
        if (ks + 2 < 16) { prefetch((ks + 2) % NSTG, (ks + 2) * BK); CP_COMMIT(); }

        const uint32_t st = sb + (ks % NSTG) * STG_SZ;
#pragma unroll
        for (int kk = 0; kk < 2; kk++) {
            const uint32_t kb = kk * 32;
            uint32_t ah[2][4], bh[4][4];
#pragma unroll
            for (int mt = 0; mt < 2; mt++)
                ldsm_x4(ah[mt], st + aoff + mt * (16 * ROWB) + kb);
#pragma unroll
            for (int nt = 0; nt < 4; nt++)
                ldsm_x4(bh[nt], st + BUF_SZ + boff + nt * (16 * ROWB) + kb);
#pragma unroll
            for (int mt = 0; mt < 2; mt++) {
#pragma unroll
                for (int nt = 0; nt < 4; nt++) {
                    mma16816(acc[mt][2 * nt + 0], ah[mt], bh[nt][0], bh[nt][2]);
                    mma16816(acc[mt][2 * nt + 1], ah[mt], bh[nt][1], bh[nt][3]);
                }
            }
        }
        __syncthreads();
    }

#pragma unroll
    for (int mt = 0; mt < 2; mt++) {
        const int row0 = m0 + wm * 32 + mt * 16 + (lane >> 2);
#pragma unroll
        for (int nt = 0; nt < 8; nt++) {
            const int col = n0 + wn * 64 + nt * 8 + (lane & 3) * 2;
            const float b0 = __ldg(&bias[col]);
            const float b1 = __ldg(&bias[col + 1]);
            float v0 = acc[mt][nt][0] + b0;
            float v1 = acc[mt][nt][1] + b1;
            float v2 = acc[mt][nt][2] + b0;
            float v3 = acc[mt][nt][3] + b1;
            v0 = (v0 > 0.f) ? (v0 + 1.f) : __expf(v0);
            v1 = (v1 > 0.f) ? (v1 + 1.f) : __expf(v1);
            v2 = (v2 > 0.f) ? (v2 + 1.f) : __expf(v2);
            v3 = (v3 > 0.f) ? (v3 + 1.f) : __expf(v3);
            *(__half2*)&g_qkh[(size_t)row0 * 1024 + col]       = __floats2half2_rn(v0, v1);
            *(__half2*)&g_qkh[(size_t)(row0 + 8) * 1024 + col] = __floats2half2_rn(v2, v3);
        }
    }
}

// ============================================================
// K3: split-K partial kv + fused kmean stage-1 (pre-RoPE k column sums)
// ============================================================
__global__ __launch_bounds__(256)
void kv_partial_kernel() {
    const int split = blockIdx.x, h = blockIdx.y, b = blockIdx.z;
    __shared__ float ks[32][64];
    __shared__ float vs[32][64];
    __shared__ float ksum[64];

    const int tid = threadIdx.x;
    const int ty = tid >> 4, tx = tid & 15;
    const int n0 = split * (N_ / SPLITS);

    if (tid < 64) ksum[tid] = 0.f;

    float acc[4][4];
#pragma unroll
    for (int i = 0; i < 4; i++)
#pragma unroll
        for (int j = 0; j < 4; j++) acc[i][j] = 0.f;

    const int kd = tid & 31;                 // fixed per thread
    const int kpair = h * 32 + kd;           // global rope pair index
    const int kk = kpair & 127;
    const bool useH = (kpair < 128);
    float sx = 0.f, sy = 0.f;                // pre-rope column sums

    for (int c0 = 0; c0 < N_ / SPLITS; c0 += 32) {
        // load + rotate K tile (32 rows x 32 pairs), fp16 source
#pragma unroll
        for (int l = 0; l < 4; l++) {
            const int row = (tid >> 5) + l * 8;
            const int n   = n0 + c0 + row;
            const __half2 khv = *(const __half2*)&g_qkh[((size_t)(b * N_ + n)) * CK_ + C_ + h * D_ + 2 * kd];
            const float2 kq = __half22float2(khv);
            sx += kq.x; sy += kq.y;
            const int pos = useH ? (n >> 6) : (n & 63);
            const int ci = pos * 128 + kk;
            const float cc = g_cos2[ci], ss = g_sin2[ci];
            float2 kr;
            kr.x = kq.x * cc - kq.y * ss;
            kr.y = kq.x * ss + kq.y * cc;
            *(float2*)&ks[row][2 * kd] = kr;
        }
        // load V tile (32 rows x 64) from fp16 x
#pragma unroll
        for (int l = 0; l < 2; l++) {
            const int p   = tid + l * 256;
            const int row = p >> 4;
            const int e4  = (p & 15) * 4;
            const int n   = n0 + c0 + row;
            const uint2 raw = *(const uint2*)&g_Af16[((size_t)(b * N_ + n)) * C_ + h * D_ + e4];
            const float2 f01 = __half22float2(*(const __half2*)&raw.x);
            const float2 f23 = __half22float2(*(const __half2*)&raw.y);
            vs[row][e4 + 0] = f01.x; vs[row][e4 + 1] = f01.y;
            vs[row][e4 + 2] = f23.x; vs[row][e4 + 3] = f23.y;
        }
        __syncthreads();

#pragma unroll
        for (int nn = 0; nn < 32; nn++) {
            float kr[4], vr[4];
#pragma unroll
            for (int i = 0; i < 4; i++) kr[i] = ks[nn][ty * 4 + i];
#pragma unroll
            for (int j = 0; j < 4; j++) vr[j] = vs[nn][tx * 4 + j];
#pragma unroll
            for (int i = 0; i < 4; i++)
#pragma unroll
                for (int j = 0; j < 4; j++) acc[i][j] += kr[i] * vr[j];
        }
        __syncthreads();
    }

    // kmean partial: reduce sx/sy (8 threads share each kd)
    atomicAdd(&ksum[2 * kd + 0], sx);
    atomicAdd(&ksum[2 * kd + 1], sy);

    float* dst = &g_kvp[(((size_t)split * B_ + b) * H_ + h) * (D_ * D_)];
#pragma unroll
    for (int i = 0; i < 4; i++)
#pragma unroll
        for (int j = 0; j < 4; j++)
            dst[(ty * 4 + i) * D_ + tx * 4 + j] = acc[i][j];

    __syncthreads();
    if (tid < 64) g_kpart[split][b][h * D_ + tid] = ksum[tid];
}

// ============================================================
// K2b: kmean final reduce
// ============================================================
__global__ __launch_bounds__(512)
void kmean_stage2() {
    const int b = blockIdx.x;
    const int col = threadIdx.x;
    float s = 0.f;
#pragma unroll
    for (int sp = 0; sp < SPLITS; sp++)
        s += g_kpart[sp][b][col];
    g_kmean[b * C_ + col] = s * (1.0f / N_);
}

// ============================================================
// K4: kv reduce
// ============================================================
__global__ void kv_reduce_kernel() {
    const int i = blockIdx.x * 256 + threadIdx.x;
    float s = 0.f;
#pragma unroll
    for (int sp = 0; sp < SPLITS; sp++)
        s += g_kvp[(size_t)sp * (B_ * H_ * D_ * D_) + i];
    g_kv[i] = s * (1.0f / N_);
}

// ============================================================
// K5: finalize, 4 hp-rows per block, fp16 halo + fp16 q reads
// dynamic smem (bytes):
//   kvs 16384 | qs 16384 | w9s 2304 | zs 256 | km 256 | xth (6*4096 half = 49152)
// ============================================================
#define FIN_FLOATS (4096 + 4096 + 576 + 64 + 64)
#define FIN_SMEM   (FIN_FLOATS * 4 + 6 * 4096 * 2)

__global__ __launch_bounds__(256)
void finalize_kernel(const float* __restrict__ LW, const float* __restrict__ LB,
                     float* __restrict__ out) {
    extern __shared__ float fsm[];
    float* kvs = fsm;                   // [64][64]
    float* qs  = kvs + 4096;            // [64][64]
    float* w9s = qs + 4096;             // [9][64]
    float* zs  = w9s + 576;             // [64]
    float* km  = zs + 64;               // [64]
    __half* xth = (__half*)(km + 64);   // [6][64][64]

    const int hp4 = blockIdx.x;         // 0..15 (4 spatial rows each)
    const int h   = blockIdx.y;
    const int b   = blockIdx.z;
    const int tid = threadIdx.x;

    // phase 1: loads
    {
        const float* kvsrc = &g_kv[((size_t)(b * H_ + h)) * (D_ * D_)];
        for (int i = tid; i < 1024; i += 256)
            ((float4*)kvs)[i] = ((const float4*)kvsrc)[i];
    }
    if (tid < 64) km[tid] = g_kmean[b * C_ + h * D_ + tid];
    for (int i = tid; i < 576; i += 256) {
        const int p = i / 64, e = i % 64;
        w9s[i] = LW[p * C_ + h * D_ + e];
    }
    // halo rows hp4*4-1 .. hp4*4+4  (6 rows x 64 w x 64 ch, fp16)
    for (int i = tid; i < 6144; i += 256) {           // uint2 quads
        const int j   = i >> 10;                       // halo row 0..5
        const int rem = i & 1023;
        const int w   = rem >> 4;
        const int e4  = (rem & 15) * 4;
        const int h2  = hp4 * 4 - 1 + j;
        uint2 raw = make_uint2(0u, 0u);
        if ((unsigned)h2 < 64u)
            raw = *(const uint2*)&g_Af16[((size_t)(b * N_ + h2 * 64 + w)) * C_ + h * D_ + e4];
        *(uint2*)&xth[j * 4096 + w * 64 + e4] = raw;
    }
    __syncthreads();

#pragma unroll 1
    for (int rp = 0; rp < 4; rp++) {
        const int hp = hp4 * 4 + rp;

        // phase 2: q-RoPE + z for 64 tokens of row hp
        {
            const int w = tid >> 5, lane = tid & 31;
            const int kpair = h * 32 + lane;
            const int kk = kpair & 127;
            const bool useH = (kpair < 128);
#pragma unroll
            for (int rr = 0; rr < 8; rr++) {
                const int r = w * 8 + rr;
                const int n = hp * 64 + r;
                const __half2 qh = *(const __half2*)&g_qkh[((size_t)(b * N_ + n)) * CK_ + h * D_ + 2 * lane];
                const float2 qv = __half22float2(qh);
                const int pos = useH ? hp : r;
                const int ci = pos * 128 + kk;
                const float cc = g_cos2[ci], ss = g_sin2[ci];
                float2 qr;
                qr.x = qv.x * cc - qv.y * ss;
                qr.y = qv.x * ss + qv.y * cc;
                *(float2*)&qs[r * 64 + 2 * lane] = qr;
                float zp = qv.x * km[2 * lane] + qv.y * km[2 * lane + 1];
#pragma unroll
                for (int o = 16; o > 0; o >>= 1) zp += __shfl_xor_sync(0xffffffffu, zp, o);
                if (lane == 0) zs[r] = 1.0f / (zp + 1e-6f);
            }
        }
        __syncthreads();

        // phase 3: matvec + lepe
        const int e = tid & 63;
        const int c = h * D_ + e;
        const float lbias = LB[c];
        for (int r = tid >> 6; r < 64; r += 4) {
            float acc = 0.f;
#pragma unroll
            for (int d = 0; d < 64; d++) acc += qs[r * 64 + d] * kvs[d * 64 + e];

            float lep = lbias;
#pragma unroll
            for (int di = 0; di < 3; di++) {
#pragma unroll
                for (int dj = 0; dj < 3; dj++) {
                    const int w2 = r + dj - 1;
                    if ((unsigned)w2 < 64u)
                        lep += __half2float(xth[(rp + di) * 4096 + w2 * 64 + e]) *
                               w9s[(di * 3 + dj) * 64 + e];
                }
            }
            out[((size_t)(b * N_ + hp * 64 + r)) * C_ + c] = acc * zs[r] + lep;
        }
        __syncthreads();
    }
}

// ============================================================
extern "C" void kernel_launch(void* const* d_in, const int* in_sizes, int n_in,
                              void* d_out, int out_size) {
    (void)in_sizes; (void)n_in; (void)out_size;
    const float* x  = (const float*)d_in[0];   // (16, 4096, 512)
    const float* W  = (const float*)d_in[1];   // (512, 1024)
    const float* qb = (const float*)d_in[2];   // (1024,)
    const float* lw = (const float*)d_in[3];   // (3,3,1,512)
    const float* lb = (const float*)d_in[4];   // (512,)
    float* out = (float*)d_out;                // (16, 4096, 512)

    cudaFuncSetAttribute(qk_gemm_mma, cudaFuncAttributeMaxDynamicSharedMemorySize, GSMEM);
    cudaFuncSetAttribute(finalize_kernel, cudaFuncAttributeMaxDynamicSharedMemorySize, FIN_SMEM);

    rope_init_kernel<<<32, 256>>>();
    convert_x_kernel<<<(int)(((size_t)B_ * N_ * C_ / 4) / 256), 256>>>(x);
    convert_w_kernel<<<(C_ * CK_) / 256, 256>>>(W);
    qk_gemm_mma<<<dim3(CK_ / 128, (B_ * N_) / 128), 256, GSMEM>>>(qb);
    kv_partial_kernel<<<dim3(SPLITS, H_, B_), 256>>>();
    kmean_stage2<<<B_, 512>>>();
    kv_reduce_kernel<<<(B_ * H_ * D_ * D_) / 256, 256>>>();
    finalize_kernel<<<dim3(16, H_, B_), 256, FIN_SMEM>>>(lw, lb, out);
}